// round 9
// baseline (speedup 1.0000x reference)
#include <cuda_runtime.h>
#include <cuda_bf16.h>
#include <cstdint>

// Skinning as split-precision bf16 GEMM via raw mma.sync.m16n8k16:
//   out[b,v,i] = sum_{j,c} F[v,4j+c] * H[4j+c,3b+i]
//   F[v,k] = w[v,j]*vh[v,c], vh=(x,y,z,1);  H[k,n] = M[b,j,i,c], n=3b+i
// GEMM M=100000 (256/CTA), N=96 (12 n8-tiles), K=208 (13 k16-tiles)
// bf16 2-split passes: Ahi*Bhi + Ahi*Blo + Alo*Bhi
//
// R9 vs R8: 2 m-tiles per warp (B frags serve 6 MMAs), B image packed so one
// fragment quad [bh0,bh1,bl0,bl1] = one LDS.128, MMA sweeps of 12 independent
// accumulators for ILP at 1 CTA/SM.

#define JJ    52
#define NDIM  96
#define KDIM  208
#define NT    13             // k16 tiles
#define TPB   256
#define MTILE 256
#define DLD   101            // f32 elems per sD row (101 mod 32 = 5: conflict-light)

// B image: block(n, t, tig) = 16 bytes [bh0 bh1 bl0 bl1]
// byte addr = ((n*NT + t)*4 + tig)*16 ; total 96*13*4*16 = 79872 B
#define SZ_BT    (NDIM * NT * 4 * 16)        // 79872
#define OFF_BT   0
#define OFF_W    SZ_BT                        // 79872
#define SZ_W     (MTILE * JJ * 4)             // 53248
#define OFF_V    (OFF_W + SZ_W)               // 133120
#define SZ_V     (MTILE * 4 * 4)              // 4096
#define SMEM_TOTAL (OFF_V + SZ_V)             // 137216

__device__ __nv_bfloat16 g_BT[SZ_BT / 2];

__device__ __forceinline__ uint32_t pack_hi(float f0, float f1)
{
    uint32_t r;
    asm("prmt.b32 %0, %1, %2, 0x7632;"
        : "=r"(r) : "r"(__float_as_uint(f0)), "r"(__float_as_uint(f1)));
    return r;
}
__device__ __forceinline__ uint32_t pack_lo(float f0, float f1)
{
    float l0 = f0 - __uint_as_float(__float_as_uint(f0) & 0xffff0000u);
    float l1 = f1 - __uint_as_float(__float_as_uint(f1) & 0xffff0000u);
    uint32_t r;
    asm("cvt.rn.bf16x2.f32 %0, %1, %2;" : "=r"(r) : "f"(l1), "f"(l0));
    return r;
}
__device__ __forceinline__ void mma16816(float* c, const uint32_t* a, uint32_t b0, uint32_t b1)
{
    asm volatile(
        "mma.sync.aligned.m16n8k16.row.col.f32.bf16.bf16.f32 "
        "{%0,%1,%2,%3}, {%4,%5,%6,%7}, {%8,%9}, {%0,%1,%2,%3};"
        : "+f"(c[0]), "+f"(c[1]), "+f"(c[2]), "+f"(c[3])
        : "r"(a[0]), "r"(a[1]), "r"(a[2]), "r"(a[3]), "r"(b0), "r"(b1));
}

// ---------------- pre-kernel: packed B image ----------------
__global__ void hbuild_kernel(const float* __restrict__ xf)
{
    int idx = blockIdx.x * blockDim.x + threadIdx.x;
    if (idx >= KDIM * NDIM) return;
    int k = idx / NDIM;
    int n = idx - k * NDIM;
    int j = k >> 2, c = k & 3;
    int b = n / 3, i = n - 3 * b;

    float f = xf[(((size_t)b * JJ + j) << 4) + (i << 2) + c];
    uint32_t fb = __float_as_uint(f);
    uint32_t hb = fb & 0xffff0000u;
    unsigned short hi = (unsigned short)(hb >> 16);
    __nv_bfloat16 lb = __float2bfloat16_rn(f - __uint_as_float(hb));
    unsigned short lo = *reinterpret_cast<unsigned short*>(&lb);

    int t    = k >> 4;
    int kin  = k & 15;
    int half = kin >> 3;          // 0 -> b0 word, 1 -> b1 word
    int tig  = (kin & 7) >> 1;
    int pos  = kin & 1;           // low/high 16 of the word
    // element index into bf16 array: block base (8 elems) + word layout
    int base = ((n * NT + t) * 4 + tig) * 8;
    g_BT[base + half * 2 + pos]     = *reinterpret_cast<__nv_bfloat16*>(&hi);  // bh
    g_BT[base + 4 + half * 2 + pos] = *reinterpret_cast<__nv_bfloat16*>(&lo);  // bl
}

// ---------------- main kernel ----------------
__global__ __launch_bounds__(TPB)
void skin_mma_kernel(const float* __restrict__ verts,
                     const float* __restrict__ w,
                     float* __restrict__ out,
                     int V)
{
    extern __shared__ __align__(16) unsigned char smem[];
    float* sW = reinterpret_cast<float*>(smem + OFF_W);   // [256][52]
    float* sV = reinterpret_cast<float*>(smem + OFF_V);   // [256][4]
    float* sD = reinterpret_cast<float*>(smem);           // aliases BT+W post-MMA

    const int tid = threadIdx.x;
    const int v0  = blockIdx.x * MTILE;

    // ---- stage B image ----
    {
        const float4* s = reinterpret_cast<const float4*>(g_BT);
        float4* d = reinterpret_cast<float4*>(smem + OFF_BT);
        for (int i = tid; i < SZ_BT / 16; i += TPB) d[i] = s[i];
    }
    // ---- stage weights ----
    for (int i = tid; i < MTILE * JJ; i += TPB) {
        int r  = i / JJ;
        int j  = i - r * JJ;
        int vv = min(v0 + r, V - 1);
        sW[i] = w[(size_t)vv * JJ + j];
    }
    // ---- stage vh ----
    for (int i = tid; i < MTILE; i += TPB) {
        int vv = min(v0 + i, V - 1);
        sV[i * 4 + 0] = verts[vv * 3 + 0];
        sV[i * 4 + 1] = verts[vv * 3 + 1];
        sV[i * 4 + 2] = verts[vv * 3 + 2];
        sV[i * 4 + 3] = 1.0f;
    }
    __syncthreads();

    // ---- fragment geometry ----
    const int warp = tid >> 5;
    const int lane = tid & 31;
    const int gid  = lane >> 2;
    const int tig  = lane & 3;
    const int c0   = (tig & 1) * 2;
    const int jadd = tig >> 1;

    // 4 owned rows: mt0 {rA0, rA0+8}, mt1 {rA0+16, rA0+24}
    const int rA0 = warp * 32 + gid;
    float vp[4][2];
#pragma unroll
    for (int q = 0; q < 4; q++) {
        vp[q][0] = sV[(rA0 + 8 * q) * 4 + c0];
        vp[q][1] = sV[(rA0 + 8 * q) * 4 + c0 + 1];
    }

    float acc[2][12][4];
#pragma unroll
    for (int mt = 0; mt < 2; mt++)
#pragma unroll
        for (int nt = 0; nt < 12; nt++)
#pragma unroll
            for (int q = 0; q < 4; q++) acc[mt][nt][q] = 0.0f;

    // B base for this thread: n = nt*8 + gid; addr = ((n*NT + t)*4 + tig)*16
    const unsigned char* bBase = smem + OFF_BT + ((size_t)gid * NT * 4 + tig) * 16;
    // strides: nt -> 8*NT*4*16 = 6656 B ; t -> 64 B

#pragma unroll 1
    for (int t = 0; t < NT; t++) {
        // ---- load all 12 B fragment quads (one LDS.128 each) ----
        uint32_t bh[12][2], bl[12][2];
#pragma unroll
        for (int nt = 0; nt < 12; nt++) {
            uint4 q = *reinterpret_cast<const uint4*>(bBase + (size_t)nt * 6656 + t * 64);
            bh[nt][0] = q.x; bh[nt][1] = q.y;
            bl[nt][0] = q.z; bl[nt][1] = q.w;
        }

        // ---- build A fragments for both m-tiles ----
        const int j0 = 4 * t + jadd;
        uint32_t ahi[2][4], alo[2][4];
#pragma unroll
        for (int mt = 0; mt < 2; mt++) {
            const int ra = rA0 + mt * 16;
            const int rb = ra + 8;
            const float w00 = sW[ra * JJ + j0];
            const float w01 = sW[ra * JJ + j0 + 2];
            const float w10 = sW[rb * JJ + j0];
            const float w11 = sW[rb * JJ + j0 + 2];
            const float* pa = vp[mt * 2];
            const float* pb = vp[mt * 2 + 1];
            float f0, f1;
            f0 = w00 * pa[0]; f1 = w00 * pa[1];
            ahi[mt][0] = pack_hi(f0, f1); alo[mt][0] = pack_lo(f0, f1);
            f0 = w10 * pb[0]; f1 = w10 * pb[1];
            ahi[mt][1] = pack_hi(f0, f1); alo[mt][1] = pack_lo(f0, f1);
            f0 = w01 * pa[0]; f1 = w01 * pa[1];
            ahi[mt][2] = pack_hi(f0, f1); alo[mt][2] = pack_lo(f0, f1);
            f0 = w11 * pb[0]; f1 = w11 * pb[1];
            ahi[mt][3] = pack_hi(f0, f1); alo[mt][3] = pack_lo(f0, f1);
        }

        // ---- 6 sweeps of 12 independent MMAs (dependents >= 12 apart) ----
#pragma unroll
        for (int nt = 0; nt < 12; nt++) mma16816(acc[0][nt], ahi[0], bh[nt][0], bh[nt][1]);
#pragma unroll
        for (int nt = 0; nt < 12; nt++) mma16816(acc[1][nt], ahi[1], bh[nt][0], bh[nt][1]);
#pragma unroll
        for (int nt = 0; nt < 12; nt++) mma16816(acc[0][nt], ahi[0], bl[nt][0], bl[nt][1]);
#pragma unroll
        for (int nt = 0; nt < 12; nt++) mma16816(acc[1][nt], ahi[1], bl[nt][0], bl[nt][1]);
#pragma unroll
        for (int nt = 0; nt < 12; nt++) mma16816(acc[0][nt], alo[0], bh[nt][0], bh[nt][1]);
#pragma unroll
        for (int nt = 0; nt < 12; nt++) mma16816(acc[1][nt], alo[1], bh[nt][0], bh[nt][1]);
    }

    __syncthreads();   // BT/W dead -> sD

    // ---- stage D: sD[256][DLD] ----
#pragma unroll
    for (int mt = 0; mt < 2; mt++) {
        const int ra = rA0 + mt * 16;
#pragma unroll
        for (int nt = 0; nt < 12; nt++) {
            const int col = nt * 8 + tig * 2;
            sD[ra * DLD + col]          = acc[mt][nt][0];
            sD[ra * DLD + col + 1]      = acc[mt][nt][1];
            sD[(ra + 8) * DLD + col]     = acc[mt][nt][2];
            sD[(ra + 8) * DLD + col + 1] = acc[mt][nt][3];
        }
    }
    __syncthreads();

    // ---- coalesced output ----
    const size_t V3 = (size_t)V * 3;
    const int nValid = min(MTILE, V - v0);
    const int lim = nValid * 3;
#pragma unroll 1
    for (int b = 0; b < 32; b++) {
        float* ob = out + (size_t)b * V3 + (size_t)v0 * 3;
        for (int idx = tid; idx < lim; idx += TPB) {
            const int vv = idx / 3;
            const int i  = idx - vv * 3;
            ob[idx] = sD[(size_t)vv * DLD + 3 * b + i];
        }
    }
}

// ---------------- launch ----------------
extern "C" void kernel_launch(void* const* d_in, const int* in_sizes, int n_in,
                              void* d_out, int out_size)
{
    const float* verts   = (const float*)d_in[0];
    const float* weights = (const float*)d_in[1];
    const float* xf      = (const float*)d_in[2];
    float*       out     = (float*)d_out;

    const int V = in_sizes[0] / 3;

    {
        const int total = KDIM * NDIM;
        hbuild_kernel<<<(total + 255) / 256, 256>>>(xf);
    }
    {
        cudaFuncSetAttribute(skin_mma_kernel,
                             cudaFuncAttributeMaxDynamicSharedMemorySize, SMEM_TOTAL);
        const int grid = (V + MTILE - 1) / MTILE;
        skin_mma_kernel<<<grid, TPB, SMEM_TOTAL>>>(verts, weights, out, V);
    }
}

// round 11
// speedup vs baseline: 1.0937x; 1.0937x over previous
#include <cuda_runtime.h>
#include <cuda_bf16.h>
#include <cstdint>

// Skinning as split-precision bf16 GEMM via raw mma.sync.m16n8k16:
//   out[b,v,i] = sum_{j,c} F[v,4j+c] * H[4j+c,3b+i]
//   F[v,k] = w[v,j]*vh[v,c], vh=(x,y,z,1);  H[k,n] = M[b,j,i,c], n=3b+i
// GEMM M=100000 (128/CTA), N=96 (12 n8-tiles), K=208 (13 k16-tiles)
// bf16 2-split passes: Ahi*Bhi + Ahi*Blo + Alo*Bhi
//
// R10 = R8 occupancy (MTILE=128, 2 CTAs/SM, 16 warps) + R9 instruction diet
// (B packed as 16B fragment quads -> LDS.128; MMA sweeps of 6 independent
// accumulators), with an explicit 128-reg budget (launch_bounds(256,2)).

#define JJ    52
#define NDIM  96
#define KDIM  208
#define NT    13             // k16 tiles
#define TPB   256
#define MTILE 128
#define DLD   101            // f32 elems per sD row

// B image: block(n, t, tig) = 16 bytes [bh0 bh1 bl0 bl1]
// byte addr = ((n*NT + t)*4 + tig)*16 ; total 96*13*4*16 = 79872 B
#define SZ_BT    (NDIM * NT * 4 * 16)        // 79872
#define OFF_BT   0
#define OFF_W    SZ_BT                        // 79872
#define SZ_W     (MTILE * JJ * 4)             // 26624
#define OFF_V    (OFF_W + SZ_W)               // 106496
#define SZ_V     (MTILE * 4 * 4)              // 2048
#define SMEM_TOTAL (OFF_V + SZ_V)             // 108544 (~106 KB, 2 CTAs/SM)

__device__ __nv_bfloat16 g_BT[SZ_BT / 2];

__device__ __forceinline__ uint32_t pack_hi(float f0, float f1)
{
    uint32_t r;
    asm("prmt.b32 %0, %1, %2, 0x7632;"
        : "=r"(r) : "r"(__float_as_uint(f0)), "r"(__float_as_uint(f1)));
    return r;
}
__device__ __forceinline__ uint32_t pack_lo(float f0, float f1)
{
    float l0 = f0 - __uint_as_float(__float_as_uint(f0) & 0xffff0000u);
    float l1 = f1 - __uint_as_float(__float_as_uint(f1) & 0xffff0000u);
    uint32_t r;
    asm("cvt.rn.bf16x2.f32 %0, %1, %2;" : "=r"(r) : "f"(l1), "f"(l0));
    return r;
}
__device__ __forceinline__ void mma16816(float* c, const uint32_t* a, uint32_t b0, uint32_t b1)
{
    asm volatile(
        "mma.sync.aligned.m16n8k16.row.col.f32.bf16.bf16.f32 "
        "{%0,%1,%2,%3}, {%4,%5,%6,%7}, {%8,%9}, {%0,%1,%2,%3};"
        : "+f"(c[0]), "+f"(c[1]), "+f"(c[2]), "+f"(c[3])
        : "r"(a[0]), "r"(a[1]), "r"(a[2]), "r"(a[3]), "r"(b0), "r"(b1));
}

// ---------------- pre-kernel: packed B image ----------------
__global__ void hbuild_kernel(const float* __restrict__ xf)
{
    int idx = blockIdx.x * blockDim.x + threadIdx.x;
    if (idx >= KDIM * NDIM) return;
    int k = idx / NDIM;
    int n = idx - k * NDIM;
    int j = k >> 2, c = k & 3;
    int b = n / 3, i = n - 3 * b;

    float f = xf[(((size_t)b * JJ + j) << 4) + (i << 2) + c];
    uint32_t fb = __float_as_uint(f);
    uint32_t hb = fb & 0xffff0000u;
    unsigned short hi = (unsigned short)(hb >> 16);
    __nv_bfloat16 lb = __float2bfloat16_rn(f - __uint_as_float(hb));
    unsigned short lo = *reinterpret_cast<unsigned short*>(&lb);

    int t    = k >> 4;
    int kin  = k & 15;
    int half = kin >> 3;          // 0 -> b0 word, 1 -> b1 word
    int tig  = (kin & 7) >> 1;
    int pos  = kin & 1;
    int base = ((n * NT + t) * 4 + tig) * 8;
    g_BT[base + half * 2 + pos]     = *reinterpret_cast<__nv_bfloat16*>(&hi);  // bh
    g_BT[base + 4 + half * 2 + pos] = *reinterpret_cast<__nv_bfloat16*>(&lo);  // bl
}

// ---------------- main kernel ----------------
__global__ __launch_bounds__(TPB, 2)
void skin_mma_kernel(const float* __restrict__ verts,
                     const float* __restrict__ w,
                     float* __restrict__ out,
                     int V)
{
    extern __shared__ __align__(16) unsigned char smem[];
    float* sW = reinterpret_cast<float*>(smem + OFF_W);   // [128][52]
    float* sV = reinterpret_cast<float*>(smem + OFF_V);   // [128][4]
    float* sD = reinterpret_cast<float*>(smem);           // aliases BT post-MMA

    const int tid = threadIdx.x;
    const int v0  = blockIdx.x * MTILE;

    // ---- stage B image ----
    {
        const float4* s = reinterpret_cast<const float4*>(g_BT);
        float4* d = reinterpret_cast<float4*>(smem + OFF_BT);
        for (int i = tid; i < SZ_BT / 16; i += TPB) d[i] = s[i];
    }
    // ---- stage weights ----
    for (int i = tid; i < MTILE * JJ; i += TPB) {
        int r  = i / JJ;
        int j  = i - r * JJ;
        int vv = min(v0 + r, V - 1);
        sW[i] = w[(size_t)vv * JJ + j];
    }
    // ---- stage vh ----
    for (int i = tid; i < MTILE; i += TPB) {
        int vv = min(v0 + i, V - 1);
        sV[i * 4 + 0] = verts[vv * 3 + 0];
        sV[i * 4 + 1] = verts[vv * 3 + 1];
        sV[i * 4 + 2] = verts[vv * 3 + 2];
        sV[i * 4 + 3] = 1.0f;
    }
    __syncthreads();

    // ---- fragment geometry ----
    const int warp = tid >> 5;
    const int lane = tid & 31;
    const int gid  = lane >> 2;
    const int tig  = lane & 3;
    const int c0   = (tig & 1) * 2;
    const int jadd = tig >> 1;

    const int r0 = warp * 16 + gid;
    const int r1 = r0 + 8;
    const float p0 = sV[r0 * 4 + c0];
    const float p1 = sV[r0 * 4 + c0 + 1];
    const float s0 = sV[r1 * 4 + c0];
    const float s1 = sV[r1 * 4 + c0 + 1];

    float acc[12][4];
#pragma unroll
    for (int nt = 0; nt < 12; nt++)
#pragma unroll
        for (int q = 0; q < 4; q++) acc[nt][q] = 0.0f;

    // B base: n = nt*8 + gid; addr = ((n*NT + t)*4 + tig)*16
    const unsigned char* bBase = smem + OFF_BT + ((size_t)gid * NT * 4 + tig) * 16;
    // strides: nt -> 8*NT*4*16 = 6656 B ; t -> 64 B

#pragma unroll 1
    for (int t = 0; t < NT; t++) {
        // ---- build A fragments in registers ----
        const int j0 = 4 * t + jadd;
        const float w00 = sW[r0 * JJ + j0];
        const float w01 = sW[r0 * JJ + j0 + 2];
        const float w10 = sW[r1 * JJ + j0];
        const float w11 = sW[r1 * JJ + j0 + 2];

        float f0, f1;
        uint32_t ahi[4], alo[4];
        f0 = w00 * p0; f1 = w00 * p1;  ahi[0] = pack_hi(f0, f1); alo[0] = pack_lo(f0, f1);
        f0 = w10 * s0; f1 = w10 * s1;  ahi[1] = pack_hi(f0, f1); alo[1] = pack_lo(f0, f1);
        f0 = w01 * p0; f1 = w01 * p1;  ahi[2] = pack_hi(f0, f1); alo[2] = pack_lo(f0, f1);
        f0 = w11 * s0; f1 = w11 * s1;  ahi[3] = pack_hi(f0, f1); alo[3] = pack_lo(f0, f1);

        const unsigned char* bt = bBase + t * 64;

        // ---- two half-batches of 6 quads; sweeps keep dependents >= 6 apart ----
#pragma unroll
        for (int h = 0; h < 2; h++) {
            uint32_t bh[6][2], bl[6][2];
#pragma unroll
            for (int q = 0; q < 6; q++) {
                uint4 quad = *reinterpret_cast<const uint4*>(bt + (size_t)(h * 6 + q) * 6656);
                bh[q][0] = quad.x; bh[q][1] = quad.y;
                bl[q][0] = quad.z; bl[q][1] = quad.w;
            }
            float (*ac)[4] = acc + h * 6;
#pragma unroll
            for (int q = 0; q < 6; q++) mma16816(ac[q], ahi, bh[q][0], bh[q][1]);
#pragma unroll
            for (int q = 0; q < 6; q++) mma16816(ac[q], ahi, bl[q][0], bl[q][1]);
#pragma unroll
            for (int q = 0; q < 6; q++) mma16816(ac[q], alo, bh[q][0], bh[q][1]);
        }
    }

    __syncthreads();   // BT region dead -> sD

    // ---- stage D: sD[128][DLD] ----
#pragma unroll
    for (int nt = 0; nt < 12; nt++) {
        const int col = nt * 8 + tig * 2;
        sD[r0 * DLD + col]     = acc[nt][0];
        sD[r0 * DLD + col + 1] = acc[nt][1];
        sD[r1 * DLD + col]     = acc[nt][2];
        sD[r1 * DLD + col + 1] = acc[nt][3];
    }
    __syncthreads();

    // ---- coalesced output ----
    const size_t V3 = (size_t)V * 3;
    const int nValid = min(MTILE, V - v0);
    const int lim = nValid * 3;
#pragma unroll 1
    for (int b = 0; b < 32; b++) {
        float* ob = out + (size_t)b * V3 + (size_t)v0 * 3;
        for (int idx = tid; idx < lim; idx += TPB) {
            const int vv = idx / 3;
            const int i  = idx - vv * 3;
            ob[idx] = sD[(size_t)vv * DLD + 3 * b + i];
        }
    }
}

// ---------------- launch ----------------
extern "C" void kernel_launch(void* const* d_in, const int* in_sizes, int n_in,
                              void* d_out, int out_size)
{
    const float* verts   = (const float*)d_in[0];
    const float* weights = (const float*)d_in[1];
    const float* xf      = (const float*)d_in[2];
    float*       out     = (float*)d_out;

    const int V = in_sizes[0] / 3;

    {
        const int total = KDIM * NDIM;
        hbuild_kernel<<<(total + 255) / 256, 256>>>(xf);
    }
    {
        cudaFuncSetAttribute(skin_mma_kernel,
                             cudaFuncAttributeMaxDynamicSharedMemorySize, SMEM_TOTAL);
        const int grid = (V + MTILE - 1) / MTILE;
        skin_mma_kernel<<<grid, TPB, SMEM_TOTAL>>>(verts, weights, out, V);
    }
}